// round 3
// baseline (speedup 1.0000x reference)
#include <cuda_runtime.h>
#include <math.h>

#define HLR   96
#define NPIX  (HLR*HLR)          // 9216
#define HS    384
#define QTOT  (HS*HS)            // 147456
#define CCH   64
#define INDIM 68

// ---------------- scratch (device globals; no runtime alloc) ----------------
__device__ __align__(16) float g_f1[CCH*NPIX];     // conv1 out (relu), [c][p]
__device__ __align__(16) float g_f2[CCH*NPIX];     // conv2 out (relu), [c][p]
__device__ __align__(16) float g_ft[NPIX*CCH];     // conv3 out, transposed [p][c]
__device__ __align__(16) float g_pred[QTOT*3];     // pred before refinement, [q][3]
__device__ __align__(16) int   g_flag[QTOT];
__device__ __align__(16) int   g_hard[QTOT];
__device__ int   g_cnt;

// ---------------- conv1: 3 -> 64, relu, out [c][p] ----------------
__global__ __launch_bounds__(256) void k_conv1(const float* __restrict__ lr,
                                               const float* __restrict__ w,
                                               const float* __restrict__ b) {
    if (blockIdx.x == 0 && threadIdx.x == 0) g_cnt = 0;
    int idx = blockIdx.x * 256 + threadIdx.x;
    if (idx >= CCH * NPIX) return;
    int oc = idx / NPIX, p = idx % NPIX;
    int y = p / HLR, x = p % HLR;
    float s = b[oc];
    #pragma unroll
    for (int ic = 0; ic < 3; ic++) {
        #pragma unroll
        for (int ky = 0; ky < 3; ky++) {
            int iy = y + ky - 1;
            if ((unsigned)iy >= HLR) continue;
            #pragma unroll
            for (int kx = 0; kx < 3; kx++) {
                int ix = x + kx - 1;
                if ((unsigned)ix >= HLR) continue;
                s += lr[ic*NPIX + iy*HLR + ix] * w[oc*27 + ic*9 + ky*3 + kx];
            }
        }
    }
    g_f1[oc*NPIX + p] = fmaxf(s, 0.f);
}

// ---------------- conv 64->64, 3x3, SAME zero pad ----------------
// stage==0: in g_f1 -> out g_f2 ([c][p]) with relu
// stage==1: in g_f2 -> out g_ft ([p][c]) no relu
__global__ __launch_bounds__(256) void k_conv64(const float* __restrict__ w,
                                                const float* __restrict__ b,
                                                int stage) {
    __shared__ float sIn[8][18][18];
    __shared__ float sW[72][32];          // [ic*9+k][oc]
    const float* in = (stage == 0) ? g_f1 : g_f2;
    int tile = blockIdx.x;
    int ty0 = (tile / 6) * 16, tx0 = (tile % 6) * 16;
    int ocBase = blockIdx.y * 32;
    int tid = threadIdx.x;
    int ty = tid / 16, tx = tid % 16;
    float acc[32];
    #pragma unroll
    for (int o = 0; o < 32; o++) acc[o] = 0.f;

    for (int cc = 0; cc < 8; cc++) {
        int icB = cc * 8;
        for (int i = tid; i < 2592; i += 256) {
            int ic = i / 324, rem = i % 324;
            int r = rem / 18, c = rem % 18;
            int gy = ty0 + r - 1, gx = tx0 + c - 1;
            sIn[ic][r][c] = ((unsigned)gy < HLR && (unsigned)gx < HLR)
                          ? in[(icB + ic)*NPIX + gy*HLR + gx] : 0.f;
        }
        for (int i = tid; i < 2304; i += 256) {
            int o = i % 32, key = i / 32;
            int ic = key / 9, k = key % 9;
            sW[key][o] = w[(ocBase + o)*576 + (icB + ic)*9 + k];
        }
        __syncthreads();
        #pragma unroll
        for (int ic = 0; ic < 8; ic++) {
            #pragma unroll
            for (int ky = 0; ky < 3; ky++) {
                #pragma unroll
                for (int kx = 0; kx < 3; kx++) {
                    float xv = sIn[ic][ty + ky][tx + kx];
                    const float4* wr = (const float4*)sW[ic*9 + ky*3 + kx];
                    #pragma unroll
                    for (int j = 0; j < 8; j++) {
                        float4 wv = wr[j];
                        acc[4*j+0] += xv * wv.x;
                        acc[4*j+1] += xv * wv.y;
                        acc[4*j+2] += xv * wv.z;
                        acc[4*j+3] += xv * wv.w;
                    }
                }
            }
        }
        __syncthreads();
    }
    int p = (ty0 + ty)*HLR + tx0 + tx;
    if (stage == 0) {
        #pragma unroll
        for (int o = 0; o < 32; o++)
            g_f2[(ocBase + o)*NPIX + p] = fmaxf(acc[o] + b[ocBase + o], 0.f);
    } else {
        #pragma unroll
        for (int o = 0; o < 32; o++)
            g_ft[p*CCH + ocBase + o] = acc[o] + b[ocBase + o];
    }
}

// ---------------- per-query: classifier + light MLP + grid sample ----------------
__global__ __launch_bounds__(256) void k_query(const float* __restrict__ coord,
                                               const float* __restrict__ cell,
                                               const float* __restrict__ lr,
                                               const float* __restrict__ wl1, const float* __restrict__ bl1,
                                               const float* __restrict__ wl2, const float* __restrict__ bl2,
                                               const float* __restrict__ wc1, const float* __restrict__ bc1,
                                               const float* __restrict__ wc2, const float* __restrict__ bc2) {
    __shared__ float sWc[INDIM*64], sWl[INDIM*64];
    __shared__ float sbc1[64], sbl1[64], swc2[128], swl2[192], sbc2[2], sbl2[3];
    int tid = threadIdx.x;
    for (int i = tid; i < INDIM*64; i += 256) { sWc[i] = wc1[i]; sWl[i] = wl1[i]; }
    if (tid < 64)  { sbc1[tid] = bc1[tid]; sbl1[tid] = bl1[tid]; }
    if (tid < 128) swc2[tid] = wc2[tid];
    if (tid < 192) swl2[tid] = wl2[tid];
    if (tid < 2)   sbc2[tid] = bc2[tid];
    if (tid < 3)   sbl2[tid] = bl2[tid];
    __syncthreads();

    int q = blockIdx.x * 256 + tid;
    if (q >= QTOT) return;

    float cy = coord[2*q], cx = coord[2*q+1];
    int iy = (int)floorf((cy + 1.f) * 0.5f * 96.f); iy = min(max(iy, 0), HLR-1);
    int ix = (int)floorf((cx + 1.f) * 0.5f * 96.f); ix = min(max(ix, 0), HLR-1);
    int fidx = iy*HLR + ix;

    float x[INDIM];
    const float4* fv = (const float4*)(g_ft + fidx*CCH);
    #pragma unroll
    for (int i = 0; i < 16; i++) {
        float4 v = fv[i];
        x[4*i] = v.x; x[4*i+1] = v.y; x[4*i+2] = v.z; x[4*i+3] = v.w;
    }
    float fy = -1.f + (2.f*iy + 1.f) / 96.f;
    float fx = -1.f + (2.f*ix + 1.f) / 96.f;
    x[64] = (cy - fy) * 96.f;
    x[65] = (cx - fx) * 96.f;
    x[66] = cell[2*q]   * 96.f;
    x[67] = cell[2*q+1] * 96.f;

    // classifier
    float l0 = sbc2[0], l1 = sbc2[1];
    for (int og = 0; og < 16; og++) {
        float4 a = make_float4(0.f,0.f,0.f,0.f);
        const float4* wp = (const float4*)(sWc + og*4);
        #pragma unroll
        for (int i = 0; i < INDIM; i++) {
            float4 wv = wp[i*16];
            a.x += x[i]*wv.x; a.y += x[i]*wv.y; a.z += x[i]*wv.z; a.w += x[i]*wv.w;
        }
        int o = og*4;
        float h0 = fmaxf(a.x + sbc1[o+0], 0.f);
        float h1 = fmaxf(a.y + sbc1[o+1], 0.f);
        float h2 = fmaxf(a.z + sbc1[o+2], 0.f);
        float h3 = fmaxf(a.w + sbc1[o+3], 0.f);
        l0 += h0*swc2[(o+0)*2] + h1*swc2[(o+1)*2] + h2*swc2[(o+2)*2] + h3*swc2[(o+3)*2];
        l1 += h0*swc2[(o+0)*2+1] + h1*swc2[(o+1)*2+1] + h2*swc2[(o+2)*2+1] + h3*swc2[(o+3)*2+1];
    }
    int flag = (l1 > l0) ? 1 : 0;

    // light MLP
    float p0 = sbl2[0], p1 = sbl2[1], p2 = sbl2[2];
    for (int og = 0; og < 16; og++) {
        float4 a = make_float4(0.f,0.f,0.f,0.f);
        const float4* wp = (const float4*)(sWl + og*4);
        #pragma unroll
        for (int i = 0; i < INDIM; i++) {
            float4 wv = wp[i*16];
            a.x += x[i]*wv.x; a.y += x[i]*wv.y; a.z += x[i]*wv.z; a.w += x[i]*wv.w;
        }
        int o = og*4;
        float h0 = fmaxf(a.x + sbl1[o+0], 0.f);
        float h1 = fmaxf(a.y + sbl1[o+1], 0.f);
        float h2 = fmaxf(a.z + sbl1[o+2], 0.f);
        float h3 = fmaxf(a.w + sbl1[o+3], 0.f);
        p0 += h0*swl2[(o+0)*3] + h1*swl2[(o+1)*3] + h2*swl2[(o+2)*3] + h3*swl2[(o+3)*3];
        p1 += h0*swl2[(o+0)*3+1] + h1*swl2[(o+1)*3+1] + h2*swl2[(o+2)*3+1] + h3*swl2[(o+3)*3+1];
        p2 += h0*swl2[(o+0)*3+2] + h1*swl2[(o+1)*3+2] + h2*swl2[(o+2)*3+2] + h3*swl2[(o+3)*3+2];
    }

    // grid sample (bilinear, border, align_corners=False) on lr
    float gy = fminf(fmaxf((cy + 1.f) * 96.f * 0.5f - 0.5f, 0.f), 95.f);
    float gx = fminf(fmaxf((cx + 1.f) * 96.f * 0.5f - 0.5f, 0.f), 95.f);
    float y0f = floorf(gy), x0f = floorf(gx);
    float wy = gy - y0f, wx = gx - x0f;
    int y0 = (int)y0f, x0 = (int)x0f;
    int y1 = min(y0 + 1, HLR-1), x1 = min(x0 + 1, HLR-1);
    float w00 = (1.f-wy)*(1.f-wx), w01 = (1.f-wy)*wx, w10 = wy*(1.f-wx), w11 = wy*wx;
    float gs[3];
    #pragma unroll
    for (int c = 0; c < 3; c++) {
        const float* pl = lr + c*NPIX;
        gs[c] = pl[y0*HLR+x0]*w00 + pl[y0*HLR+x1]*w01
              + pl[y1*HLR+x0]*w10 + pl[y1*HLR+x1]*w11;
    }

    float base = flag ? 0.f : 1.f;
    g_pred[3*q+0] = base*p0 + gs[0];
    g_pred[3*q+1] = base*p1 + gs[1];
    g_pred[3*q+2] = base*p2 + gs[2];
    g_flag[q] = flag;

    // warp-aggregated compaction of hard queries
    unsigned mask = __ballot_sync(0xffffffffu, flag);
    if (mask) {
        int lane = tid & 31;
        int leader = __ffs(mask) - 1;
        int basePos = 0;
        if (lane == leader) basePos = atomicAdd(&g_cnt, __popc(mask));
        basePos = __shfl_sync(0xffffffffu, basePos, leader);
        if (flag) g_hard[basePos + __popc(mask & ((1u << lane) - 1u))] = q;
    }
}

// ---------------- heavy MLP (persistent, 64-query tiles, SGEMM-style) ----------------
// smem layout (floats): As0[16384] | As1[16384] | Bs[16384] | sQ[64 ints]
#define SM_AS0 0
#define SM_AS1 16384
#define SM_BS  32768
#define SM_FLOATS 49152
#define SMEM_HEAVY (SM_FLOATS*4 + 256)

__device__ __forceinline__ void mlp_layer(const float* A, const float* __restrict__ Wg,
                                          const float* __restrict__ Bg, int K,
                                          float* Ao, float* Bs) {
    int tid = threadIdx.x;
    int tn = tid & 31, tm = tid >> 5;
    float acc[8][8];
    #pragma unroll
    for (int i = 0; i < 8; i++)
        #pragma unroll
        for (int j = 0; j < 8; j++) acc[i][j] = 0.f;

    for (int kb = 0; kb < K; kb += 64) {
        int kc = min(64, K - kb);
        for (int i = tid; i < kc*64; i += 256) {          // float4 units, row=64 float4
            int kk = i >> 6, n4 = i & 63;
            ((float4*)Bs)[kk*64 + n4] = ((const float4*)Wg)[(kb+kk)*64 + n4];
        }
        __syncthreads();
        for (int kk = 0; kk < kc; kk++) {
            const float* Ar = A + (kb+kk)*64 + tm*8;
            float4 a0 = *(const float4*)(Ar);
            float4 a1 = *(const float4*)(Ar + 4);
            const float* Br = Bs + kk*256 + tn*8;
            float4 b0 = *(const float4*)(Br);
            float4 b1 = *(const float4*)(Br + 4);
            float am[8] = {a0.x,a0.y,a0.z,a0.w,a1.x,a1.y,a1.z,a1.w};
            float bn[8] = {b0.x,b0.y,b0.z,b0.w,b1.x,b1.y,b1.z,b1.w};
            #pragma unroll
            for (int i = 0; i < 8; i++)
                #pragma unroll
                for (int j = 0; j < 8; j++) acc[i][j] += am[i]*bn[j];
        }
        __syncthreads();
    }
    // bias + relu + transposed store: Ao[n*64 + m]
    #pragma unroll
    for (int j = 0; j < 8; j++) {
        int nn = tn*8 + j;
        float bb = Bg[nn];
        float4 w0 = make_float4(fmaxf(acc[0][j]+bb,0.f), fmaxf(acc[1][j]+bb,0.f),
                                fmaxf(acc[2][j]+bb,0.f), fmaxf(acc[3][j]+bb,0.f));
        float4 w1 = make_float4(fmaxf(acc[4][j]+bb,0.f), fmaxf(acc[5][j]+bb,0.f),
                                fmaxf(acc[6][j]+bb,0.f), fmaxf(acc[7][j]+bb,0.f));
        *(float4*)(Ao + nn*64 + tm*8)     = w0;
        *(float4*)(Ao + nn*64 + tm*8 + 4) = w1;
    }
    __syncthreads();
}

__global__ __launch_bounds__(256, 1) void k_heavy(const float* __restrict__ coord,
                                                  const float* __restrict__ cell,
                                                  const float* __restrict__ wh1, const float* __restrict__ bh1,
                                                  const float* __restrict__ wh2, const float* __restrict__ bh2,
                                                  const float* __restrict__ wh3, const float* __restrict__ bh3,
                                                  const float* __restrict__ wh4, const float* __restrict__ bh4) {
    extern __shared__ float sm[];
    float* As0 = sm + SM_AS0;
    float* As1 = sm + SM_AS1;
    float* Bs  = sm + SM_BS;
    int*   sQ  = (int*)(sm + SM_FLOATS);
    int tid = threadIdx.x;

    int n = *((volatile int*)&g_cnt);
    if (n <= 0) return;
    int tiles = (n + 63) >> 6;

    for (int t = blockIdx.x; t < tiles; t += gridDim.x) {
        int base = t * 64;
        if (tid < 64) sQ[tid] = (base + tid < n) ? g_hard[base + tid] : -1;
        __syncthreads();

        // build X (68 x 64, k-major) into As1
        {
            int m = tid & 63, part = tid >> 6;
            int qv = sQ[m];
            int q = qv < 0 ? 0 : qv;
            float cy = coord[2*q], cx = coord[2*q+1];
            int iy = (int)floorf((cy + 1.f)*0.5f*96.f); iy = min(max(iy,0), HLR-1);
            int ix = (int)floorf((cx + 1.f)*0.5f*96.f); ix = min(max(ix,0), HLR-1);
            int fb = (iy*HLR + ix)*CCH;
            #pragma unroll
            for (int j = 0; j < 16; j++) {
                int k = part*16 + j;
                As1[k*64 + m] = g_ft[fb + k];
            }
            if (part == 0) {
                float fy = -1.f + (2.f*iy + 1.f)/96.f;
                float fx = -1.f + (2.f*ix + 1.f)/96.f;
                As1[64*64 + m] = (cy - fy)*96.f;
                As1[65*64 + m] = (cx - fx)*96.f;
                As1[66*64 + m] = cell[2*q]   * 96.f;
                As1[67*64 + m] = cell[2*q+1] * 96.f;
            }
        }
        __syncthreads();

        mlp_layer(As1, wh1, bh1, 68,  As0, Bs);   // h1
        mlp_layer(As0, wh2, bh2, 256, As1, Bs);   // h2
        mlp_layer(As1, wh3, bh3, 256, As0, Bs);   // h3

        if (tid < 192) {
            int m = tid & 63, c = tid >> 6;
            float s0 = 0.f, s1 = 0.f, s2 = 0.f, s3 = 0.f;
            #pragma unroll 4
            for (int k = 0; k < 256; k += 4) {
                s0 += As0[(k+0)*64 + m] * wh4[(k+0)*3 + c];
                s1 += As0[(k+1)*64 + m] * wh4[(k+1)*3 + c];
                s2 += As0[(k+2)*64 + m] * wh4[(k+2)*3 + c];
                s3 += As0[(k+3)*64 + m] * wh4[(k+3)*3 + c];
            }
            int qv = sQ[m];
            if (qv >= 0) g_pred[qv*3 + c] += s0 + s1 + s2 + s3 + bh4[c];
        }
        __syncthreads();
    }
}

// ---------------- refinement + output ----------------
__global__ __launch_bounds__(256) void k_refine(float* __restrict__ out, int out_size) {
    int q = blockIdx.x * 256 + threadIdx.x;
    if (q >= QTOT) return;
    int y = q / HS, x = q % HS;
    int flag = g_flag[q];
    float v0 = g_pred[3*q], v1 = g_pred[3*q+1], v2 = g_pred[3*q+2];

    if (y > 0 && y < HS-1 && x > 0 && x < HS-1 && flag == 0) {
        int fs = 0;
        #pragma unroll
        for (int dy = -1; dy <= 1; dy++)
            #pragma unroll
            for (int dx = -1; dx <= 1; dx++)
                fs += g_flag[(y+dy)*HS + x + dx];
        if (fs > 0) {
            float s0 = 0.f, s1 = 0.f, s2 = 0.f;
            #pragma unroll
            for (int dy = -1; dy <= 1; dy++)
                #pragma unroll
                for (int dx = -1; dx <= 1; dx++) {
                    int qq = (y+dy)*HS + x + dx;
                    s0 += g_pred[3*qq]; s1 += g_pred[3*qq+1]; s2 += g_pred[3*qq+2];
                }
            v0 = s0 / 9.f; v1 = s1 / 9.f; v2 = s2 / 9.f;
        }
    }
    out[3*q]   = v0;
    out[3*q+1] = v1;
    out[3*q+2] = v2;
    if (out_size >= 4*QTOT) out[3*QTOT + q] = (float)flag;
}

// ---------------- launcher ----------------
extern "C" void kernel_launch(void* const* d_in, const int* in_sizes, int n_in,
                              void* d_out, int out_size) {
    const float* lr    = (const float*)d_in[0];
    const float* coord = (const float*)d_in[1];
    const float* cell  = (const float*)d_in[2];
    const float* ew1 = (const float*)d_in[3];  const float* eb1 = (const float*)d_in[4];
    const float* ew2 = (const float*)d_in[5];  const float* eb2 = (const float*)d_in[6];
    const float* ew3 = (const float*)d_in[7];  const float* eb3 = (const float*)d_in[8];
    const float* wh1 = (const float*)d_in[9];  const float* bh1 = (const float*)d_in[10];
    const float* wh2 = (const float*)d_in[11]; const float* bh2 = (const float*)d_in[12];
    const float* wh3 = (const float*)d_in[13]; const float* bh3 = (const float*)d_in[14];
    const float* wh4 = (const float*)d_in[15]; const float* bh4 = (const float*)d_in[16];
    const float* wl1 = (const float*)d_in[17]; const float* bl1 = (const float*)d_in[18];
    const float* wl2 = (const float*)d_in[19]; const float* bl2 = (const float*)d_in[20];
    const float* wc1 = (const float*)d_in[21]; const float* bc1 = (const float*)d_in[22];
    const float* wc2 = (const float*)d_in[23]; const float* bc2 = (const float*)d_in[24];

    (void)cudaFuncSetAttribute(k_heavy, cudaFuncAttributeMaxDynamicSharedMemorySize, SMEM_HEAVY);

    k_conv1<<<(CCH*NPIX + 255)/256, 256>>>(lr, ew1, eb1);
    k_conv64<<<dim3(36, 2), 256>>>(ew2, eb2, 0);
    k_conv64<<<dim3(36, 2), 256>>>(ew3, eb3, 1);
    k_query<<<QTOT/256, 256>>>(coord, cell, lr,
                               wl1, bl1, wl2, bl2, wc1, bc1, wc2, bc2);
    k_heavy<<<148, 256, SMEM_HEAVY>>>(coord, cell,
                                      wh1, bh1, wh2, bh2, wh3, bh3, wh4, bh4);
    k_refine<<<QTOT/256, 256>>>((float*)d_out, out_size);
}

// round 4
// speedup vs baseline: 1.9557x; 1.9557x over previous
#include <cuda_runtime.h>
#include <math.h>

#define HLR   96
#define NPIX  (HLR*HLR)          // 9216
#define HS    384
#define QTOT  (HS*HS)            // 147456
#define CCH   64
#define INDIM 68

// ---------------- scratch (device globals; no runtime alloc) ----------------
__device__ __align__(16) float g_f1[CCH*NPIX];     // conv1 out (relu), [c][p]
__device__ __align__(16) float g_f2[CCH*NPIX];     // conv2 out (relu), [c][p]
__device__ __align__(16) float g_ft[NPIX*CCH];     // conv3 out, transposed [p][c]
__device__ __align__(16) float g_pred[QTOT*3];     // pred before refinement, [q][3]
__device__ __align__(16) int   g_flag[QTOT];
__device__ __align__(16) int   g_hard[QTOT];
__device__ int   g_cnt;

// ---------------- conv1: 3 -> 64, relu, out [c][p] ----------------
__global__ __launch_bounds__(256) void k_conv1(const float* __restrict__ lr,
                                               const float* __restrict__ w,
                                               const float* __restrict__ b) {
    if (blockIdx.x == 0 && threadIdx.x == 0) g_cnt = 0;
    int idx = blockIdx.x * 256 + threadIdx.x;
    if (idx >= CCH * NPIX) return;
    int oc = idx / NPIX, p = idx % NPIX;
    int y = p / HLR, x = p % HLR;
    float s = b[oc];
    #pragma unroll
    for (int ic = 0; ic < 3; ic++) {
        #pragma unroll
        for (int ky = 0; ky < 3; ky++) {
            int iy = y + ky - 1;
            if ((unsigned)iy >= HLR) continue;
            #pragma unroll
            for (int kx = 0; kx < 3; kx++) {
                int ix = x + kx - 1;
                if ((unsigned)ix >= HLR) continue;
                s += lr[ic*NPIX + iy*HLR + ix] * w[oc*27 + ic*9 + ky*3 + kx];
            }
        }
    }
    g_f1[oc*NPIX + p] = fmaxf(s, 0.f);
}

// ---------------- conv 64->64, 3x3, SAME zero pad ----------------
__global__ __launch_bounds__(256) void k_conv64(const float* __restrict__ w,
                                                const float* __restrict__ b,
                                                int stage) {
    __shared__ float sIn[8][18][18];
    __shared__ float sW[72][32];          // [ic*9+k][oc]
    const float* in = (stage == 0) ? g_f1 : g_f2;
    int tile = blockIdx.x;
    int ty0 = (tile / 6) * 16, tx0 = (tile % 6) * 16;
    int ocBase = blockIdx.y * 32;
    int tid = threadIdx.x;
    int ty = tid / 16, tx = tid % 16;
    float acc[32];
    #pragma unroll
    for (int o = 0; o < 32; o++) acc[o] = 0.f;

    for (int cc = 0; cc < 8; cc++) {
        int icB = cc * 8;
        for (int i = tid; i < 2592; i += 256) {
            int ic = i / 324, rem = i % 324;
            int r = rem / 18, c = rem % 18;
            int gy = ty0 + r - 1, gx = tx0 + c - 1;
            sIn[ic][r][c] = ((unsigned)gy < HLR && (unsigned)gx < HLR)
                          ? in[(icB + ic)*NPIX + gy*HLR + gx] : 0.f;
        }
        for (int i = tid; i < 2304; i += 256) {
            int o = i % 32, key = i / 32;
            int ic = key / 9, k = key % 9;
            sW[key][o] = w[(ocBase + o)*576 + (icB + ic)*9 + k];
        }
        __syncthreads();
        #pragma unroll
        for (int ic = 0; ic < 8; ic++) {
            #pragma unroll
            for (int ky = 0; ky < 3; ky++) {
                #pragma unroll
                for (int kx = 0; kx < 3; kx++) {
                    float xv = sIn[ic][ty + ky][tx + kx];
                    const float4* wr = (const float4*)sW[ic*9 + ky*3 + kx];
                    #pragma unroll
                    for (int j = 0; j < 8; j++) {
                        float4 wv = wr[j];
                        acc[4*j+0] += xv * wv.x;
                        acc[4*j+1] += xv * wv.y;
                        acc[4*j+2] += xv * wv.z;
                        acc[4*j+3] += xv * wv.w;
                    }
                }
            }
        }
        __syncthreads();
    }
    int p = (ty0 + ty)*HLR + tx0 + tx;
    if (stage == 0) {
        #pragma unroll
        for (int o = 0; o < 32; o++)
            g_f2[(ocBase + o)*NPIX + p] = fmaxf(acc[o] + b[ocBase + o], 0.f);
    } else {
        #pragma unroll
        for (int o = 0; o < 32; o++)
            g_ft[p*CCH + ocBase + o] = acc[o] + b[ocBase + o];
    }
}

// ---------------- per-query: classifier + light MLP + grid sample ----------------
__global__ __launch_bounds__(256) void k_query(const float* __restrict__ coord,
                                               const float* __restrict__ cell,
                                               const float* __restrict__ lr,
                                               const float* __restrict__ wl1, const float* __restrict__ bl1,
                                               const float* __restrict__ wl2, const float* __restrict__ bl2,
                                               const float* __restrict__ wc1, const float* __restrict__ bc1,
                                               const float* __restrict__ wc2, const float* __restrict__ bc2) {
    __shared__ float sWc[INDIM*64], sWl[INDIM*64];
    __shared__ float sbc1[64], sbl1[64], swc2[128], swl2[192], sbc2[2], sbl2[3];
    int tid = threadIdx.x;
    for (int i = tid; i < INDIM*64; i += 256) { sWc[i] = wc1[i]; sWl[i] = wl1[i]; }
    if (tid < 64)  { sbc1[tid] = bc1[tid]; sbl1[tid] = bl1[tid]; }
    if (tid < 128) swc2[tid] = wc2[tid];
    if (tid < 192) swl2[tid] = wl2[tid];
    if (tid < 2)   sbc2[tid] = bc2[tid];
    if (tid < 3)   sbl2[tid] = bl2[tid];
    __syncthreads();

    int q = blockIdx.x * 256 + tid;
    if (q >= QTOT) return;

    float cy = coord[2*q], cx = coord[2*q+1];
    int iy = (int)floorf((cy + 1.f) * 0.5f * 96.f); iy = min(max(iy, 0), HLR-1);
    int ix = (int)floorf((cx + 1.f) * 0.5f * 96.f); ix = min(max(ix, 0), HLR-1);
    int fidx = iy*HLR + ix;

    float x[INDIM];
    const float4* fv = (const float4*)(g_ft + fidx*CCH);
    #pragma unroll
    for (int i = 0; i < 16; i++) {
        float4 v = fv[i];
        x[4*i] = v.x; x[4*i+1] = v.y; x[4*i+2] = v.z; x[4*i+3] = v.w;
    }
    float fy = -1.f + (2.f*iy + 1.f) / 96.f;
    float fx = -1.f + (2.f*ix + 1.f) / 96.f;
    x[64] = (cy - fy) * 96.f;
    x[65] = (cx - fx) * 96.f;
    x[66] = cell[2*q]   * 96.f;
    x[67] = cell[2*q+1] * 96.f;

    // classifier
    float l0 = sbc2[0], l1 = sbc2[1];
    for (int og = 0; og < 16; og++) {
        float4 a = make_float4(0.f,0.f,0.f,0.f);
        const float4* wp = (const float4*)(sWc + og*4);
        #pragma unroll
        for (int i = 0; i < INDIM; i++) {
            float4 wv = wp[i*16];
            a.x += x[i]*wv.x; a.y += x[i]*wv.y; a.z += x[i]*wv.z; a.w += x[i]*wv.w;
        }
        int o = og*4;
        float h0 = fmaxf(a.x + sbc1[o+0], 0.f);
        float h1 = fmaxf(a.y + sbc1[o+1], 0.f);
        float h2 = fmaxf(a.z + sbc1[o+2], 0.f);
        float h3 = fmaxf(a.w + sbc1[o+3], 0.f);
        l0 += h0*swc2[(o+0)*2] + h1*swc2[(o+1)*2] + h2*swc2[(o+2)*2] + h3*swc2[(o+3)*2];
        l1 += h0*swc2[(o+0)*2+1] + h1*swc2[(o+1)*2+1] + h2*swc2[(o+2)*2+1] + h3*swc2[(o+3)*2+1];
    }
    int flag = (l1 > l0) ? 1 : 0;

    // light MLP
    float p0 = sbl2[0], p1 = sbl2[1], p2 = sbl2[2];
    for (int og = 0; og < 16; og++) {
        float4 a = make_float4(0.f,0.f,0.f,0.f);
        const float4* wp = (const float4*)(sWl + og*4);
        #pragma unroll
        for (int i = 0; i < INDIM; i++) {
            float4 wv = wp[i*16];
            a.x += x[i]*wv.x; a.y += x[i]*wv.y; a.z += x[i]*wv.z; a.w += x[i]*wv.w;
        }
        int o = og*4;
        float h0 = fmaxf(a.x + sbl1[o+0], 0.f);
        float h1 = fmaxf(a.y + sbl1[o+1], 0.f);
        float h2 = fmaxf(a.z + sbl1[o+2], 0.f);
        float h3 = fmaxf(a.w + sbl1[o+3], 0.f);
        p0 += h0*swl2[(o+0)*3] + h1*swl2[(o+1)*3] + h2*swl2[(o+2)*3] + h3*swl2[(o+3)*3];
        p1 += h0*swl2[(o+0)*3+1] + h1*swl2[(o+1)*3+1] + h2*swl2[(o+2)*3+1] + h3*swl2[(o+3)*3+1];
        p2 += h0*swl2[(o+0)*3+2] + h1*swl2[(o+1)*3+2] + h2*swl2[(o+2)*3+2] + h3*swl2[(o+3)*3+2];
    }

    // grid sample (bilinear, border, align_corners=False) on lr
    float gy = fminf(fmaxf((cy + 1.f) * 96.f * 0.5f - 0.5f, 0.f), 95.f);
    float gx = fminf(fmaxf((cx + 1.f) * 96.f * 0.5f - 0.5f, 0.f), 95.f);
    float y0f = floorf(gy), x0f = floorf(gx);
    float wy = gy - y0f, wx = gx - x0f;
    int y0 = (int)y0f, x0 = (int)x0f;
    int y1 = min(y0 + 1, HLR-1), x1 = min(x0 + 1, HLR-1);
    float w00 = (1.f-wy)*(1.f-wx), w01 = (1.f-wy)*wx, w10 = wy*(1.f-wx), w11 = wy*wx;
    float gs[3];
    #pragma unroll
    for (int c = 0; c < 3; c++) {
        const float* pl = lr + c*NPIX;
        gs[c] = pl[y0*HLR+x0]*w00 + pl[y0*HLR+x1]*w01
              + pl[y1*HLR+x0]*w10 + pl[y1*HLR+x1]*w11;
    }

    float base = flag ? 0.f : 1.f;
    g_pred[3*q+0] = base*p0 + gs[0];
    g_pred[3*q+1] = base*p1 + gs[1];
    g_pred[3*q+2] = base*p2 + gs[2];
    g_flag[q] = flag;

    unsigned mask = __ballot_sync(0xffffffffu, flag);
    if (mask) {
        int lane = tid & 31;
        int leader = __ffs(mask) - 1;
        int basePos = 0;
        if (lane == leader) basePos = atomicAdd(&g_cnt, __popc(mask));
        basePos = __shfl_sync(0xffffffffu, basePos, leader);
        if (flag) g_hard[basePos + __popc(mask & ((1u << lane) - 1u))] = q;
    }
}

// ---------------- heavy MLP via tf32 mma.sync ----------------
// SMEM floats: As0[64*260] | As1[64*260] | Bs[72*260] | sQ[64 ints]
#define SP    260
#define AS0F  0
#define AS1F  16640
#define BSF   33280
#define SQF   52000
#define SMEM_HEAVY (52000*4 + 256)

__device__ __forceinline__ float tf32r(float f) {
    unsigned u;
    asm("cvt.rna.tf32.f32 %0, %1;" : "=r"(u) : "f"(f));
    return __uint_as_float(u);
}

__device__ __forceinline__ void mma8(float* d, unsigned a0, unsigned a1,
                                     unsigned a2, unsigned a3,
                                     unsigned b0, unsigned b1) {
    asm volatile(
        "mma.sync.aligned.m16n8k8.row.col.f32.tf32.tf32.f32 "
        "{%0,%1,%2,%3}, {%4,%5,%6,%7}, {%8,%9}, {%0,%1,%2,%3};"
        : "+f"(d[0]), "+f"(d[1]), "+f"(d[2]), "+f"(d[3])
        : "r"(a0), "r"(a1), "r"(a2), "r"(a3), "r"(b0), "r"(b1));
}

// One layer: Ain[64][SP] (tf32-rounded values), W[Kw][256] global, bias[256].
// Out: Aout[64][SP], relu, optional tf32 rounding for next MMA layer.
__device__ __forceinline__ void mma_layer(const float* Ain,
                                          const float* __restrict__ Wg,
                                          const float* __restrict__ Bg,
                                          int Kw, float* Bs, float* Aout,
                                          int do_cvt) {
    int tid  = threadIdx.x;
    int w    = tid >> 5, lane = tid & 31;
    int g    = lane >> 2, r = lane & 3;
    int mbase = (w & 1) * 32;
    int nbase = (w >> 1) * 64;

    float acc[2][8][4];
    #pragma unroll
    for (int t = 0; t < 2; t++)
        #pragma unroll
        for (int nt = 0; nt < 8; nt++)
            #pragma unroll
            for (int j = 0; j < 4; j++) acc[t][nt][j] = 0.f;

    int Kpad = (Kw == INDIM) ? 72 : Kw;
    int kc   = (Kpad == 72) ? 72 : 64;

    for (int kb = 0; kb < Kpad; kb += kc) {
        __syncthreads();
        // stage weight chunk (tf32-rounded)
        for (int i = tid; i < kc * 64; i += 256) {
            int row = i >> 6, c4 = i & 63;
            float4 v;
            if (kb + row < Kw) v = ((const float4*)Wg)[(kb + row) * 64 + c4];
            else               v = make_float4(0.f, 0.f, 0.f, 0.f);
            v.x = tf32r(v.x); v.y = tf32r(v.y); v.z = tf32r(v.z); v.w = tf32r(v.w);
            *(float4*)(Bs + row * SP + c4 * 4) = v;
        }
        __syncthreads();

        int nks = kc >> 3;
        for (int ks = 0; ks < nks; ks++) {
            const float* Ap = Ain + kb + ks * 8 + r;
            unsigned a[8];
            int r0 = (mbase + g) * SP, r1 = (mbase + g + 8) * SP;
            int r2 = (mbase + g + 16) * SP, r3 = (mbase + g + 24) * SP;
            a[0] = __float_as_uint(Ap[r0]);     a[1] = __float_as_uint(Ap[r1]);
            a[2] = __float_as_uint(Ap[r0 + 4]); a[3] = __float_as_uint(Ap[r1 + 4]);
            a[4] = __float_as_uint(Ap[r2]);     a[5] = __float_as_uint(Ap[r3]);
            a[6] = __float_as_uint(Ap[r2 + 4]); a[7] = __float_as_uint(Ap[r3 + 4]);

            const float* Br0 = Bs + (ks * 8 + r) * SP + nbase + g;
            const float* Br1 = Br0 + 4 * SP;
            #pragma unroll
            for (int nt = 0; nt < 8; nt++) {
                unsigned b0 = __float_as_uint(Br0[nt * 8]);
                unsigned b1 = __float_as_uint(Br1[nt * 8]);
                mma8(acc[0][nt], a[0], a[1], a[2], a[3], b0, b1);
                mma8(acc[1][nt], a[4], a[5], a[6], a[7], b0, b1);
            }
        }
    }

    // epilogue: bias + relu (+ tf32 round), write Aout
    #pragma unroll
    for (int nt = 0; nt < 8; nt++) {
        int c0 = nbase + nt * 8 + r * 2;
        float bb0 = __ldg(Bg + c0), bb1 = __ldg(Bg + c0 + 1);
        #pragma unroll
        for (int t = 0; t < 2; t++) {
            int row0 = mbase + t * 16 + g;
            float d0 = fmaxf(acc[t][nt][0] + bb0, 0.f);
            float d1 = fmaxf(acc[t][nt][1] + bb1, 0.f);
            float d2 = fmaxf(acc[t][nt][2] + bb0, 0.f);
            float d3 = fmaxf(acc[t][nt][3] + bb1, 0.f);
            if (do_cvt) { d0 = tf32r(d0); d1 = tf32r(d1); d2 = tf32r(d2); d3 = tf32r(d3); }
            *(float2*)(Aout + row0 * SP + c0)       = make_float2(d0, d1);
            *(float2*)(Aout + (row0 + 8) * SP + c0) = make_float2(d2, d3);
        }
    }
}

__global__ __launch_bounds__(256, 1) void k_heavy(const float* __restrict__ coord,
                                                  const float* __restrict__ cell,
                                                  const float* __restrict__ wh1, const float* __restrict__ bh1,
                                                  const float* __restrict__ wh2, const float* __restrict__ bh2,
                                                  const float* __restrict__ wh3, const float* __restrict__ bh3,
                                                  const float* __restrict__ wh4, const float* __restrict__ bh4) {
    extern __shared__ float sm[];
    float* As0 = sm + AS0F;
    float* As1 = sm + AS1F;
    float* Bs  = sm + BSF;
    int*   sQ  = (int*)(sm + SQF);
    int tid = threadIdx.x;

    int n = *((volatile int*)&g_cnt);
    if (n <= 0) return;
    int tiles = (n + 63) >> 6;

    for (int t = blockIdx.x; t < tiles; t += gridDim.x) {
        __syncthreads();                       // protect sQ / As from previous tile
        int base = t * 64;
        if (tid < 64) sQ[tid] = (base + tid < n) ? g_hard[base + tid] : -1;
        __syncthreads();

        // stage X (64 queries x 72 cols, tf32-rounded) into As0
        {
            int m = tid >> 2, qpart = tid & 3;
            int qv = sQ[m];
            int q = qv < 0 ? 0 : qv;
            float cy = coord[2*q], cx = coord[2*q+1];
            int iy = (int)floorf((cy + 1.f)*0.5f*96.f); iy = min(max(iy,0), HLR-1);
            int ix = (int)floorf((cx + 1.f)*0.5f*96.f); ix = min(max(ix,0), HLR-1);
            int fb = (iy*HLR + ix)*CCH;
            float* dst = As0 + m * SP;
            #pragma unroll
            for (int j = 0; j < 4; j++) {
                float4 v = *(const float4*)(g_ft + fb + qpart*16 + j*4);
                v.x = tf32r(v.x); v.y = tf32r(v.y); v.z = tf32r(v.z); v.w = tf32r(v.w);
                *(float4*)(dst + qpart*16 + j*4) = v;
            }
            if (qpart == 0) {
                float fy = -1.f + (2.f*iy + 1.f)/96.f;
                float fx = -1.f + (2.f*ix + 1.f)/96.f;
                float4 e;
                e.x = tf32r((cy - fy)*96.f);
                e.y = tf32r((cx - fx)*96.f);
                e.z = tf32r(cell[2*q]   * 96.f);
                e.w = tf32r(cell[2*q+1] * 96.f);
                *(float4*)(dst + 64) = e;
                *(float4*)(dst + 68) = make_float4(0.f, 0.f, 0.f, 0.f);
            }
        }
        // (mma_layer's first internal __syncthreads orders X-write vs A-read)
        mma_layer(As0, wh1, bh1, INDIM, Bs, As1, 1);   // h1: 68->256
        mma_layer(As1, wh2, bh2, 256,   Bs, As0, 1);   // h2: 256->256
        mma_layer(As0, wh3, bh3, 256,   Bs, As1, 0);   // h3: 256->256 (fp32 out)
        __syncthreads();

        // layer4: 256 -> 3 (fp32 SIMT) + writeback
        if (tid < 192) {
            int m = tid & 63, c = tid >> 6;
            const float* Ar = As1 + m * SP;
            float s0 = 0.f, s1 = 0.f, s2 = 0.f, s3 = 0.f;
            #pragma unroll 4
            for (int k = 0; k < 256; k += 4) {
                s0 += Ar[k+0] * wh4[(k+0)*3 + c];
                s1 += Ar[k+1] * wh4[(k+1)*3 + c];
                s2 += Ar[k+2] * wh4[(k+2)*3 + c];
                s3 += Ar[k+3] * wh4[(k+3)*3 + c];
            }
            int qv = sQ[m];
            if (qv >= 0) g_pred[qv*3 + c] += s0 + s1 + s2 + s3 + bh4[c];
        }
    }
}

// ---------------- refinement + output ----------------
__global__ __launch_bounds__(256) void k_refine(float* __restrict__ out, int out_size) {
    int q = blockIdx.x * 256 + threadIdx.x;
    if (q >= QTOT) return;
    int y = q / HS, x = q % HS;
    int flag = g_flag[q];
    float v0 = g_pred[3*q], v1 = g_pred[3*q+1], v2 = g_pred[3*q+2];

    if (y > 0 && y < HS-1 && x > 0 && x < HS-1 && flag == 0) {
        int fs = 0;
        #pragma unroll
        for (int dy = -1; dy <= 1; dy++)
            #pragma unroll
            for (int dx = -1; dx <= 1; dx++)
                fs += g_flag[(y+dy)*HS + x + dx];
        if (fs > 0) {
            float s0 = 0.f, s1 = 0.f, s2 = 0.f;
            #pragma unroll
            for (int dy = -1; dy <= 1; dy++)
                #pragma unroll
                for (int dx = -1; dx <= 1; dx++) {
                    int qq = (y+dy)*HS + x + dx;
                    s0 += g_pred[3*qq]; s1 += g_pred[3*qq+1]; s2 += g_pred[3*qq+2];
                }
            v0 = s0 / 9.f; v1 = s1 / 9.f; v2 = s2 / 9.f;
        }
    }
    out[3*q]   = v0;
    out[3*q+1] = v1;
    out[3*q+2] = v2;
    if (out_size >= 4*QTOT) out[3*QTOT + q] = (float)flag;
}

// ---------------- launcher ----------------
extern "C" void kernel_launch(void* const* d_in, const int* in_sizes, int n_in,
                              void* d_out, int out_size) {
    const float* lr    = (const float*)d_in[0];
    const float* coord = (const float*)d_in[1];
    const float* cell  = (const float*)d_in[2];
    const float* ew1 = (const float*)d_in[3];  const float* eb1 = (const float*)d_in[4];
    const float* ew2 = (const float*)d_in[5];  const float* eb2 = (const float*)d_in[6];
    const float* ew3 = (const float*)d_in[7];  const float* eb3 = (const float*)d_in[8];
    const float* wh1 = (const float*)d_in[9];  const float* bh1 = (const float*)d_in[10];
    const float* wh2 = (const float*)d_in[11]; const float* bh2 = (const float*)d_in[12];
    const float* wh3 = (const float*)d_in[13]; const float* bh3 = (const float*)d_in[14];
    const float* wh4 = (const float*)d_in[15]; const float* bh4 = (const float*)d_in[16];
    const float* wl1 = (const float*)d_in[17]; const float* bl1 = (const float*)d_in[18];
    const float* wl2 = (const float*)d_in[19]; const float* bl2 = (const float*)d_in[20];
    const float* wc1 = (const float*)d_in[21]; const float* bc1 = (const float*)d_in[22];
    const float* wc2 = (const float*)d_in[23]; const float* bc2 = (const float*)d_in[24];

    (void)cudaFuncSetAttribute(k_heavy, cudaFuncAttributeMaxDynamicSharedMemorySize, SMEM_HEAVY);

    k_conv1<<<(CCH*NPIX + 255)/256, 256>>>(lr, ew1, eb1);
    k_conv64<<<dim3(36, 2), 256>>>(ew2, eb2, 0);
    k_conv64<<<dim3(36, 2), 256>>>(ew3, eb3, 1);
    k_query<<<QTOT/256, 256>>>(coord, cell, lr,
                               wl1, bl1, wl2, bl2, wc1, bc1, wc2, bc2);
    k_heavy<<<148, 256, SMEM_HEAVY>>>(coord, cell,
                                      wh1, bh1, wh2, bh2, wh3, bh3, wh4, bh4);
    k_refine<<<QTOT/256, 256>>>((float*)d_out, out_size);
}

// round 5
// speedup vs baseline: 2.4191x; 1.2369x over previous
#include <cuda_runtime.h>
#include <math.h>

#define HLR   96
#define NPIX  (HLR*HLR)          // 9216
#define HS    384
#define QTOT  (HS*HS)            // 147456
#define CCH   64
#define INDIM 68

// ---------------- scratch (device globals; no runtime alloc) ----------------
__device__ __align__(16) float g_f1[CCH*NPIX];     // conv1 out (relu), [c][p]
__device__ __align__(16) float g_f2[CCH*NPIX];     // conv2 out (relu), [c][p]
__device__ __align__(16) float g_ft[NPIX*CCH];     // conv3 out, transposed [p][c]
__device__ __align__(16) float g_pred[QTOT*3];     // pred before refinement, [q][3]
__device__ __align__(16) int   g_flag[QTOT];
__device__ __align__(16) int   g_hard[QTOT];
__device__ int   g_cnt;

// ---------------- conv1: 3 -> 64, relu, out [c][p] ----------------
__global__ __launch_bounds__(256) void k_conv1(const float* __restrict__ lr,
                                               const float* __restrict__ w,
                                               const float* __restrict__ b) {
    if (blockIdx.x == 0 && threadIdx.x == 0) g_cnt = 0;
    int idx = blockIdx.x * 256 + threadIdx.x;
    if (idx >= CCH * NPIX) return;
    int oc = idx / NPIX, p = idx % NPIX;
    int y = p / HLR, x = p % HLR;
    float s = b[oc];
    #pragma unroll
    for (int ic = 0; ic < 3; ic++) {
        #pragma unroll
        for (int ky = 0; ky < 3; ky++) {
            int iy = y + ky - 1;
            if ((unsigned)iy >= HLR) continue;
            #pragma unroll
            for (int kx = 0; kx < 3; kx++) {
                int ix = x + kx - 1;
                if ((unsigned)ix >= HLR) continue;
                s += lr[ic*NPIX + iy*HLR + ix] * w[oc*27 + ic*9 + ky*3 + kx];
            }
        }
    }
    g_f1[oc*NPIX + p] = fmaxf(s, 0.f);
}

// ---------------- conv 64->64, 3x3, SAME zero pad (16 oc per CTA) ----------------
__global__ __launch_bounds__(256) void k_conv64(const float* __restrict__ w,
                                                const float* __restrict__ b,
                                                int stage) {
    __shared__ float sIn[8][18][18];
    __shared__ float sW[72][16];          // [ic*9+k][oc]
    const float* in = (stage == 0) ? g_f1 : g_f2;
    int tile = blockIdx.x;
    int ty0 = (tile / 6) * 16, tx0 = (tile % 6) * 16;
    int ocBase = blockIdx.y * 16;
    int tid = threadIdx.x;
    int ty = tid / 16, tx = tid % 16;
    float acc[16];
    #pragma unroll
    for (int o = 0; o < 16; o++) acc[o] = 0.f;

    for (int cc = 0; cc < 8; cc++) {
        int icB = cc * 8;
        for (int i = tid; i < 2592; i += 256) {
            int ic = i / 324, rem = i % 324;
            int r = rem / 18, c = rem % 18;
            int gy = ty0 + r - 1, gx = tx0 + c - 1;
            sIn[ic][r][c] = ((unsigned)gy < HLR && (unsigned)gx < HLR)
                          ? in[(icB + ic)*NPIX + gy*HLR + gx] : 0.f;
        }
        for (int i = tid; i < 1152; i += 256) {
            int o = i % 16, key = i / 16;
            int ic = key / 9, k = key % 9;
            sW[key][o] = w[(ocBase + o)*576 + (icB + ic)*9 + k];
        }
        __syncthreads();
        #pragma unroll
        for (int ic = 0; ic < 8; ic++) {
            #pragma unroll
            for (int ky = 0; ky < 3; ky++) {
                #pragma unroll
                for (int kx = 0; kx < 3; kx++) {
                    float xv = sIn[ic][ty + ky][tx + kx];
                    const float4* wr = (const float4*)sW[ic*9 + ky*3 + kx];
                    #pragma unroll
                    for (int j = 0; j < 4; j++) {
                        float4 wv = wr[j];
                        acc[4*j+0] += xv * wv.x;
                        acc[4*j+1] += xv * wv.y;
                        acc[4*j+2] += xv * wv.z;
                        acc[4*j+3] += xv * wv.w;
                    }
                }
            }
        }
        __syncthreads();
    }
    int p = (ty0 + ty)*HLR + tx0 + tx;
    if (stage == 0) {
        #pragma unroll
        for (int o = 0; o < 16; o++)
            g_f2[(ocBase + o)*NPIX + p] = fmaxf(acc[o] + b[ocBase + o], 0.f);
    } else {
        #pragma unroll
        for (int o = 0; o < 16; o++)
            g_ft[p*CCH + ocBase + o] = acc[o] + b[ocBase + o];
    }
}

// ---------------- per-query: classifier + light MLP + grid sample ----------------
__global__ __launch_bounds__(256) void k_query(const float* __restrict__ coord,
                                               const float* __restrict__ cell,
                                               const float* __restrict__ lr,
                                               const float* __restrict__ wl1, const float* __restrict__ bl1,
                                               const float* __restrict__ wl2, const float* __restrict__ bl2,
                                               const float* __restrict__ wc1, const float* __restrict__ bc1,
                                               const float* __restrict__ wc2, const float* __restrict__ bc2) {
    __shared__ float sWc[INDIM*64], sWl[INDIM*64];
    __shared__ float sbc1[64], sbl1[64], swc2[128], swl2[192], sbc2[2], sbl2[3];
    int tid = threadIdx.x;
    for (int i = tid; i < INDIM*64; i += 256) { sWc[i] = wc1[i]; sWl[i] = wl1[i]; }
    if (tid < 64)  { sbc1[tid] = bc1[tid]; sbl1[tid] = bl1[tid]; }
    if (tid < 128) swc2[tid] = wc2[tid];
    if (tid < 192) swl2[tid] = wl2[tid];
    if (tid < 2)   sbc2[tid] = bc2[tid];
    if (tid < 3)   sbl2[tid] = bl2[tid];
    __syncthreads();

    int q = blockIdx.x * 256 + tid;
    if (q >= QTOT) return;

    float cy = coord[2*q], cx = coord[2*q+1];
    int iy = (int)floorf((cy + 1.f) * 0.5f * 96.f); iy = min(max(iy, 0), HLR-1);
    int ix = (int)floorf((cx + 1.f) * 0.5f * 96.f); ix = min(max(ix, 0), HLR-1);
    int fidx = iy*HLR + ix;

    float x[INDIM];
    const float4* fv = (const float4*)(g_ft + fidx*CCH);
    #pragma unroll
    for (int i = 0; i < 16; i++) {
        float4 v = fv[i];
        x[4*i] = v.x; x[4*i+1] = v.y; x[4*i+2] = v.z; x[4*i+3] = v.w;
    }
    float fy = -1.f + (2.f*iy + 1.f) / 96.f;
    float fx = -1.f + (2.f*ix + 1.f) / 96.f;
    x[64] = (cy - fy) * 96.f;
    x[65] = (cx - fx) * 96.f;
    x[66] = cell[2*q]   * 96.f;
    x[67] = cell[2*q+1] * 96.f;

    // classifier (fp32 — flag precision is load-bearing)
    float l0 = sbc2[0], l1 = sbc2[1];
    for (int og = 0; og < 16; og++) {
        float4 a = make_float4(0.f,0.f,0.f,0.f);
        const float4* wp = (const float4*)(sWc + og*4);
        #pragma unroll
        for (int i = 0; i < INDIM; i++) {
            float4 wv = wp[i*16];
            a.x += x[i]*wv.x; a.y += x[i]*wv.y; a.z += x[i]*wv.z; a.w += x[i]*wv.w;
        }
        int o = og*4;
        float h0 = fmaxf(a.x + sbc1[o+0], 0.f);
        float h1 = fmaxf(a.y + sbc1[o+1], 0.f);
        float h2 = fmaxf(a.z + sbc1[o+2], 0.f);
        float h3 = fmaxf(a.w + sbc1[o+3], 0.f);
        l0 += h0*swc2[(o+0)*2] + h1*swc2[(o+1)*2] + h2*swc2[(o+2)*2] + h3*swc2[(o+3)*2];
        l1 += h0*swc2[(o+0)*2+1] + h1*swc2[(o+1)*2+1] + h2*swc2[(o+2)*2+1] + h3*swc2[(o+3)*2+1];
    }
    int flag = (l1 > l0) ? 1 : 0;

    // light MLP — only where its result is used (flag==0)
    float p0 = 0.f, p1 = 0.f, p2 = 0.f;
    if (!flag) {
        p0 = sbl2[0]; p1 = sbl2[1]; p2 = sbl2[2];
        for (int og = 0; og < 16; og++) {
            float4 a = make_float4(0.f,0.f,0.f,0.f);
            const float4* wp = (const float4*)(sWl + og*4);
            #pragma unroll
            for (int i = 0; i < INDIM; i++) {
                float4 wv = wp[i*16];
                a.x += x[i]*wv.x; a.y += x[i]*wv.y; a.z += x[i]*wv.z; a.w += x[i]*wv.w;
            }
            int o = og*4;
            float h0 = fmaxf(a.x + sbl1[o+0], 0.f);
            float h1 = fmaxf(a.y + sbl1[o+1], 0.f);
            float h2 = fmaxf(a.z + sbl1[o+2], 0.f);
            float h3 = fmaxf(a.w + sbl1[o+3], 0.f);
            p0 += h0*swl2[(o+0)*3] + h1*swl2[(o+1)*3] + h2*swl2[(o+2)*3] + h3*swl2[(o+3)*3];
            p1 += h0*swl2[(o+0)*3+1] + h1*swl2[(o+1)*3+1] + h2*swl2[(o+2)*3+1] + h3*swl2[(o+3)*3+1];
            p2 += h0*swl2[(o+0)*3+2] + h1*swl2[(o+1)*3+2] + h2*swl2[(o+2)*3+2] + h3*swl2[(o+3)*3+2];
        }
    }

    // grid sample (bilinear, border, align_corners=False) on lr
    float gy = fminf(fmaxf((cy + 1.f) * 96.f * 0.5f - 0.5f, 0.f), 95.f);
    float gx = fminf(fmaxf((cx + 1.f) * 96.f * 0.5f - 0.5f, 0.f), 95.f);
    float y0f = floorf(gy), x0f = floorf(gx);
    float wy = gy - y0f, wx = gx - x0f;
    int y0 = (int)y0f, x0 = (int)x0f;
    int y1 = min(y0 + 1, HLR-1), x1 = min(x0 + 1, HLR-1);
    float w00 = (1.f-wy)*(1.f-wx), w01 = (1.f-wy)*wx, w10 = wy*(1.f-wx), w11 = wy*wx;
    float gs[3];
    #pragma unroll
    for (int c = 0; c < 3; c++) {
        const float* pl = lr + c*NPIX;
        gs[c] = pl[y0*HLR+x0]*w00 + pl[y0*HLR+x1]*w01
              + pl[y1*HLR+x0]*w10 + pl[y1*HLR+x1]*w11;
    }

    g_pred[3*q+0] = p0 + gs[0];
    g_pred[3*q+1] = p1 + gs[1];
    g_pred[3*q+2] = p2 + gs[2];
    g_flag[q] = flag;

    unsigned mask = __ballot_sync(0xffffffffu, flag);
    if (mask) {
        int lane = tid & 31;
        int leader = __ffs(mask) - 1;
        int basePos = 0;
        if (lane == leader) basePos = atomicAdd(&g_cnt, __popc(mask));
        basePos = __shfl_sync(0xffffffffu, basePos, leader);
        if (flag) g_hard[basePos + __popc(mask & ((1u << lane) - 1u))] = q;
    }
}

// ---------------- heavy MLP via tf32 mma.sync, 128-query tiles, in-place A ----------------
// SMEM floats: As[128*260] | Bs[72*260] | sQ[128 ints]
#define SP    260
#define ASF   0
#define BSF   33280
#define SQF   52000
#define SMEM_HEAVY (52000*4 + 512)

__device__ __forceinline__ float tf32r(float f) {
    unsigned u;
    asm("cvt.rna.tf32.f32 %0, %1;" : "=r"(u) : "f"(f));
    return __uint_as_float(u);
}

__device__ __forceinline__ void mma8(float* d, unsigned a0, unsigned a1,
                                     unsigned a2, unsigned a3,
                                     unsigned b0, unsigned b1) {
    asm volatile(
        "mma.sync.aligned.m16n8k8.row.col.f32.tf32.tf32.f32 "
        "{%0,%1,%2,%3}, {%4,%5,%6,%7}, {%8,%9}, {%0,%1,%2,%3};"
        : "+f"(d[0]), "+f"(d[1]), "+f"(d[2]), "+f"(d[3])
        : "r"(a0), "r"(a1), "r"(a2), "r"(a3), "r"(b0), "r"(b1));
}

// One layer IN-PLACE on As[128][SP]. Reads k-cols [0,Kw), writes out-cols [0,256).
// All reads complete (sync) before writes. Weights W[Kw][256] global.
__device__ __forceinline__ void mma_layer(float* As,
                                          const float* __restrict__ Wg,
                                          const float* __restrict__ Bg,
                                          int Kw, float* Bs, int do_cvt) {
    int tid  = threadIdx.x;
    int w    = tid >> 5, lane = tid & 31;
    int g    = lane >> 2, r = lane & 3;
    int mbase = (w & 1) * 64;
    int nbase = (w >> 1) * 64;

    float acc[4][8][4];
    #pragma unroll
    for (int mt = 0; mt < 4; mt++)
        #pragma unroll
        for (int nt = 0; nt < 8; nt++)
            #pragma unroll
            for (int j = 0; j < 4; j++) acc[mt][nt][j] = 0.f;

    int Kpad = (Kw == INDIM) ? 72 : Kw;
    int kc   = (Kpad == 72) ? 72 : 64;

    for (int kb = 0; kb < Kpad; kb += kc) {
        __syncthreads();
        for (int i = tid; i < kc * 64; i += 256) {
            int row = i >> 6, c4 = i & 63;
            float4 v;
            if (kb + row < Kw) v = ((const float4*)Wg)[(kb + row) * 64 + c4];
            else               v = make_float4(0.f, 0.f, 0.f, 0.f);
            v.x = tf32r(v.x); v.y = tf32r(v.y); v.z = tf32r(v.z); v.w = tf32r(v.w);
            *(float4*)(Bs + row * SP + c4 * 4) = v;
        }
        __syncthreads();

        int nks = kc >> 3;
        for (int ks = 0; ks < nks; ks++) {
            const float* Ap = As + kb + ks * 8 + r;
            unsigned a[4][4];
            #pragma unroll
            for (int mt = 0; mt < 4; mt++) {
                int rowa = (mbase + mt * 16 + g) * SP;
                a[mt][0] = __float_as_uint(Ap[rowa]);
                a[mt][1] = __float_as_uint(Ap[rowa + 8 * SP]);
                a[mt][2] = __float_as_uint(Ap[rowa + 4]);
                a[mt][3] = __float_as_uint(Ap[rowa + 8 * SP + 4]);
            }
            const float* Br0 = Bs + (ks * 8 + r) * SP + nbase + g;
            const float* Br1 = Br0 + 4 * SP;
            #pragma unroll
            for (int nt = 0; nt < 8; nt++) {
                unsigned b0 = __float_as_uint(Br0[nt * 8]);
                unsigned b1 = __float_as_uint(Br1[nt * 8]);
                #pragma unroll
                for (int mt = 0; mt < 4; mt++)
                    mma8(acc[mt][nt], a[mt][0], a[mt][1], a[mt][2], a[mt][3], b0, b1);
            }
        }
    }
    __syncthreads();   // ALL As reads done before in-place writes

    #pragma unroll
    for (int nt = 0; nt < 8; nt++) {
        int c0 = nbase + nt * 8 + r * 2;
        float bb0 = __ldg(Bg + c0), bb1 = __ldg(Bg + c0 + 1);
        #pragma unroll
        for (int mt = 0; mt < 4; mt++) {
            int row0 = mbase + mt * 16 + g;
            float d0 = fmaxf(acc[mt][nt][0] + bb0, 0.f);
            float d1 = fmaxf(acc[mt][nt][1] + bb1, 0.f);
            float d2 = fmaxf(acc[mt][nt][2] + bb0, 0.f);
            float d3 = fmaxf(acc[mt][nt][3] + bb1, 0.f);
            if (do_cvt) { d0 = tf32r(d0); d1 = tf32r(d1); d2 = tf32r(d2); d3 = tf32r(d3); }
            *(float2*)(As + row0 * SP + c0)       = make_float2(d0, d1);
            *(float2*)(As + (row0 + 8) * SP + c0) = make_float2(d2, d3);
        }
    }
}

__global__ __launch_bounds__(256, 1) void k_heavy(const float* __restrict__ coord,
                                                  const float* __restrict__ cell,
                                                  const float* __restrict__ wh1, const float* __restrict__ bh1,
                                                  const float* __restrict__ wh2, const float* __restrict__ bh2,
                                                  const float* __restrict__ wh3, const float* __restrict__ bh3,
                                                  const float* __restrict__ wh4, const float* __restrict__ bh4) {
    extern __shared__ float sm[];
    float* As = sm + ASF;
    float* Bs = sm + BSF;
    int*   sQ = (int*)(sm + SQF);
    int tid = threadIdx.x;

    int n = *((volatile int*)&g_cnt);
    if (n <= 0) return;
    int tiles = (n + 127) >> 7;

    for (int t = blockIdx.x; t < tiles; t += gridDim.x) {
        __syncthreads();                       // previous tile fully consumed
        int base = t * 128;
        if (tid < 128) sQ[tid] = (base + tid < n) ? g_hard[base + tid] : -1;
        __syncthreads();

        // stage X (128 queries x 72 cols, tf32-rounded) into As
        {
            int m = tid >> 1, qpart = tid & 1;
            int qv = sQ[m];
            int q = qv < 0 ? 0 : qv;
            float cy = coord[2*q], cx = coord[2*q+1];
            int iy = (int)floorf((cy + 1.f)*0.5f*96.f); iy = min(max(iy,0), HLR-1);
            int ix = (int)floorf((cx + 1.f)*0.5f*96.f); ix = min(max(ix,0), HLR-1);
            int fb = (iy*HLR + ix)*CCH;
            float* dst = As + m * SP;
            #pragma unroll
            for (int j = 0; j < 8; j++) {
                float4 v = *(const float4*)(g_ft + fb + qpart*32 + j*4);
                v.x = tf32r(v.x); v.y = tf32r(v.y); v.z = tf32r(v.z); v.w = tf32r(v.w);
                *(float4*)(dst + qpart*32 + j*4) = v;
            }
            if (qpart) {
                float fy = -1.f + (2.f*iy + 1.f)/96.f;
                float fx = -1.f + (2.f*ix + 1.f)/96.f;
                float4 e;
                e.x = tf32r((cy - fy)*96.f);
                e.y = tf32r((cx - fx)*96.f);
                e.z = tf32r(cell[2*q]   * 96.f);
                e.w = tf32r(cell[2*q+1] * 96.f);
                *(float4*)(dst + 64) = e;
                *(float4*)(dst + 68) = make_float4(0.f, 0.f, 0.f, 0.f);
            }
        }
        // (mma_layer's first internal sync orders X writes vs A reads)
        mma_layer(As, wh1, bh1, INDIM, Bs, 1);   // h1: 68->256
        mma_layer(As, wh2, bh2, 256,   Bs, 1);   // h2: 256->256
        mma_layer(As, wh3, bh3, 256,   Bs, 0);   // h3: 256->256 (fp32 out)
        __syncthreads();                          // epilogue writes visible

        // layer4: 256 -> 3 (fp32 SIMT) + writeback
        for (int i = tid; i < 384; i += 256) {
            int m = i & 127, c = i >> 7;
            const float* Ar = As + m * SP;
            float s0 = 0.f, s1 = 0.f, s2 = 0.f, s3 = 0.f;
            #pragma unroll 4
            for (int k = 0; k < 256; k += 4) {
                s0 += Ar[k+0] * wh4[(k+0)*3 + c];
                s1 += Ar[k+1] * wh4[(k+1)*3 + c];
                s2 += Ar[k+2] * wh4[(k+2)*3 + c];
                s3 += Ar[k+3] * wh4[(k+3)*3 + c];
            }
            int qv = sQ[m];
            if (qv >= 0) g_pred[qv*3 + c] += s0 + s1 + s2 + s3 + bh4[c];
        }
    }
}

// ---------------- refinement + output ----------------
__global__ __launch_bounds__(256) void k_refine(float* __restrict__ out, int out_size) {
    int q = blockIdx.x * 256 + threadIdx.x;
    if (q >= QTOT) return;
    int y = q / HS, x = q % HS;
    int flag = g_flag[q];
    float v0 = g_pred[3*q], v1 = g_pred[3*q+1], v2 = g_pred[3*q+2];

    if (y > 0 && y < HS-1 && x > 0 && x < HS-1 && flag == 0) {
        int fs = 0;
        #pragma unroll
        for (int dy = -1; dy <= 1; dy++)
            #pragma unroll
            for (int dx = -1; dx <= 1; dx++)
                fs += g_flag[(y+dy)*HS + x + dx];
        if (fs > 0) {
            float s0 = 0.f, s1 = 0.f, s2 = 0.f;
            #pragma unroll
            for (int dy = -1; dy <= 1; dy++)
                #pragma unroll
                for (int dx = -1; dx <= 1; dx++) {
                    int qq = (y+dy)*HS + x + dx;
                    s0 += g_pred[3*qq]; s1 += g_pred[3*qq+1]; s2 += g_pred[3*qq+2];
                }
            v0 = s0 / 9.f; v1 = s1 / 9.f; v2 = s2 / 9.f;
        }
    }
    out[3*q]   = v0;
    out[3*q+1] = v1;
    out[3*q+2] = v2;
    if (out_size >= 4*QTOT) out[3*QTOT + q] = (float)flag;
}

// ---------------- launcher ----------------
extern "C" void kernel_launch(void* const* d_in, const int* in_sizes, int n_in,
                              void* d_out, int out_size) {
    const float* lr    = (const float*)d_in[0];
    const float* coord = (const float*)d_in[1];
    const float* cell  = (const float*)d_in[2];
    const float* ew1 = (const float*)d_in[3];  const float* eb1 = (const float*)d_in[4];
    const float* ew2 = (const float*)d_in[5];  const float* eb2 = (const float*)d_in[6];
    const float* ew3 = (const float*)d_in[7];  const float* eb3 = (const float*)d_in[8];
    const float* wh1 = (const float*)d_in[9];  const float* bh1 = (const float*)d_in[10];
    const float* wh2 = (const float*)d_in[11]; const float* bh2 = (const float*)d_in[12];
    const float* wh3 = (const float*)d_in[13]; const float* bh3 = (const float*)d_in[14];
    const float* wh4 = (const float*)d_in[15]; const float* bh4 = (const float*)d_in[16];
    const float* wl1 = (const float*)d_in[17]; const float* bl1 = (const float*)d_in[18];
    const float* wl2 = (const float*)d_in[19]; const float* bl2 = (const float*)d_in[20];
    const float* wc1 = (const float*)d_in[21]; const float* bc1 = (const float*)d_in[22];
    const float* wc2 = (const float*)d_in[23]; const float* bc2 = (const float*)d_in[24];

    (void)cudaFuncSetAttribute(k_heavy, cudaFuncAttributeMaxDynamicSharedMemorySize, SMEM_HEAVY);

    k_conv1<<<(CCH*NPIX + 255)/256, 256>>>(lr, ew1, eb1);
    k_conv64<<<dim3(36, 4), 256>>>(ew2, eb2, 0);
    k_conv64<<<dim3(36, 4), 256>>>(ew3, eb3, 1);
    k_query<<<QTOT/256, 256>>>(coord, cell, lr,
                               wl1, bl1, wl2, bl2, wc1, bc1, wc2, bc2);
    k_heavy<<<148, 256, SMEM_HEAVY>>>(coord, cell,
                                      wh1, bh1, wh2, bh2, wh3, bh3, wh4, bh4);
    k_refine<<<QTOT/256, 256>>>((float*)d_out, out_size);
}

// round 6
// speedup vs baseline: 2.5947x; 1.0726x over previous
#include <cuda_runtime.h>
#include <math.h>

#define HLR   96
#define NPIX  (HLR*HLR)          // 9216
#define HS    384
#define QTOT  (HS*HS)            // 147456
#define CCH   64
#define INDIM 68

// ---------------- scratch (device globals; no runtime alloc) ----------------
__device__ __align__(16) float g_f1[CCH*NPIX];     // conv1 out (relu), [c][p]
__device__ __align__(16) float g_f2[CCH*NPIX];     // conv2 out (relu), [c][p]
__device__ __align__(16) float g_ft[NPIX*CCH];     // conv3 out, transposed [p][c]
__device__ __align__(16) float g_pred[QTOT*3];     // pred before refinement, [q][3]
__device__ __align__(16) int   g_flag[QTOT];
__device__ __align__(16) int   g_hard[QTOT];
__device__ int   g_cnt;
// pre-rounded (tf32) heavy weights, K padded to multiples of 32
__device__ __align__(16) float g_w1r[96*256];
__device__ __align__(16) float g_w2r[256*256];
__device__ __align__(16) float g_w3r[256*256];

__device__ __forceinline__ float tf32r(float f) {
    unsigned u;
    asm("cvt.rna.tf32.f32 %0, %1;" : "=r"(u) : "f"(f));
    return __uint_as_float(u);
}

// ---------------- weight pre-rounding ----------------
__global__ __launch_bounds__(256) void k_prep(const float* __restrict__ wh1,
                                              const float* __restrict__ wh2,
                                              const float* __restrict__ wh3) {
    int idx = blockIdx.x * 256 + threadIdx.x;
    if (idx < 96*256) {
        int row = idx >> 8, c = idx & 255;
        g_w1r[idx] = (row < INDIM) ? tf32r(wh1[row*256 + c]) : 0.f;
    } else if (idx < 96*256 + 65536) {
        int j = idx - 96*256;
        g_w2r[j] = tf32r(wh2[j]);
    } else if (idx < 96*256 + 131072) {
        int j = idx - 96*256 - 65536;
        g_w3r[j] = tf32r(wh3[j]);
    }
}

// ---------------- conv1: 3 -> 64, relu, out [c][p] ----------------
__global__ __launch_bounds__(256) void k_conv1(const float* __restrict__ lr,
                                               const float* __restrict__ w,
                                               const float* __restrict__ b) {
    if (blockIdx.x == 0 && threadIdx.x == 0) g_cnt = 0;
    int idx = blockIdx.x * 256 + threadIdx.x;
    if (idx >= CCH * NPIX) return;
    int oc = idx / NPIX, p = idx % NPIX;
    int y = p / HLR, x = p % HLR;
    float s = b[oc];
    #pragma unroll
    for (int ic = 0; ic < 3; ic++) {
        #pragma unroll
        for (int ky = 0; ky < 3; ky++) {
            int iy = y + ky - 1;
            if ((unsigned)iy >= HLR) continue;
            #pragma unroll
            for (int kx = 0; kx < 3; kx++) {
                int ix = x + kx - 1;
                if ((unsigned)ix >= HLR) continue;
                s += lr[ic*NPIX + iy*HLR + ix] * w[oc*27 + ic*9 + ky*3 + kx];
            }
        }
    }
    g_f1[oc*NPIX + p] = fmaxf(s, 0.f);
}

// ---------------- conv 64->64, 3x3, SAME zero pad (16 oc per CTA) ----------------
__global__ __launch_bounds__(256) void k_conv64(const float* __restrict__ w,
                                                const float* __restrict__ b,
                                                int stage) {
    __shared__ float sIn[8][18][18];
    __shared__ float sW[72][16];
    const float* in = (stage == 0) ? g_f1 : g_f2;
    int tile = blockIdx.x;
    int ty0 = (tile / 6) * 16, tx0 = (tile % 6) * 16;
    int ocBase = blockIdx.y * 16;
    int tid = threadIdx.x;
    int ty = tid / 16, tx = tid % 16;
    float acc[16];
    #pragma unroll
    for (int o = 0; o < 16; o++) acc[o] = 0.f;

    for (int cc = 0; cc < 8; cc++) {
        int icB = cc * 8;
        for (int i = tid; i < 2592; i += 256) {
            int ic = i / 324, rem = i % 324;
            int r = rem / 18, c = rem % 18;
            int gy = ty0 + r - 1, gx = tx0 + c - 1;
            sIn[ic][r][c] = ((unsigned)gy < HLR && (unsigned)gx < HLR)
                          ? in[(icB + ic)*NPIX + gy*HLR + gx] : 0.f;
        }
        for (int i = tid; i < 1152; i += 256) {
            int o = i % 16, key = i / 16;
            int ic = key / 9, k = key % 9;
            sW[key][o] = w[(ocBase + o)*576 + (icB + ic)*9 + k];
        }
        __syncthreads();
        #pragma unroll
        for (int ic = 0; ic < 8; ic++) {
            #pragma unroll
            for (int ky = 0; ky < 3; ky++) {
                #pragma unroll
                for (int kx = 0; kx < 3; kx++) {
                    float xv = sIn[ic][ty + ky][tx + kx];
                    const float4* wr = (const float4*)sW[ic*9 + ky*3 + kx];
                    #pragma unroll
                    for (int j = 0; j < 4; j++) {
                        float4 wv = wr[j];
                        acc[4*j+0] += xv * wv.x;
                        acc[4*j+1] += xv * wv.y;
                        acc[4*j+2] += xv * wv.z;
                        acc[4*j+3] += xv * wv.w;
                    }
                }
            }
        }
        __syncthreads();
    }
    int p = (ty0 + ty)*HLR + tx0 + tx;
    if (stage == 0) {
        #pragma unroll
        for (int o = 0; o < 16; o++)
            g_f2[(ocBase + o)*NPIX + p] = fmaxf(acc[o] + b[ocBase + o], 0.f);
    } else {
        #pragma unroll
        for (int o = 0; o < 16; o++)
            g_ft[p*CCH + ocBase + o] = acc[o] + b[ocBase + o];
    }
}

// ---------------- per-query: classifier + light MLP + grid sample (128 thr) ----------------
__global__ __launch_bounds__(128) void k_query(const float* __restrict__ coord,
                                               const float* __restrict__ cell,
                                               const float* __restrict__ lr,
                                               const float* __restrict__ wl1, const float* __restrict__ bl1,
                                               const float* __restrict__ wl2, const float* __restrict__ bl2,
                                               const float* __restrict__ wc1, const float* __restrict__ bc1,
                                               const float* __restrict__ wc2, const float* __restrict__ bc2) {
    __shared__ float sWc[INDIM*64], sWl[INDIM*64];
    __shared__ float sbc1[64], sbl1[64], swc2[128], swl2[192], sbc2[2], sbl2[3];
    int tid = threadIdx.x;
    for (int i = tid; i < INDIM*64; i += 128) { sWc[i] = wc1[i]; sWl[i] = wl1[i]; }
    if (tid < 64)  { sbc1[tid] = bc1[tid]; sbl1[tid] = bl1[tid]; }
    if (tid < 128) swc2[tid] = wc2[tid];
    for (int i = tid; i < 192; i += 128) swl2[i] = wl2[i];
    if (tid < 2)   sbc2[tid] = bc2[tid];
    if (tid < 3)   sbl2[tid] = bl2[tid];
    __syncthreads();

    int q = blockIdx.x * 128 + tid;
    if (q >= QTOT) return;

    float cy = coord[2*q], cx = coord[2*q+1];
    int iy = (int)floorf((cy + 1.f) * 0.5f * 96.f); iy = min(max(iy, 0), HLR-1);
    int ix = (int)floorf((cx + 1.f) * 0.5f * 96.f); ix = min(max(ix, 0), HLR-1);
    int fidx = iy*HLR + ix;

    float x[INDIM];
    const float4* fv = (const float4*)(g_ft + fidx*CCH);
    #pragma unroll
    for (int i = 0; i < 16; i++) {
        float4 v = fv[i];
        x[4*i] = v.x; x[4*i+1] = v.y; x[4*i+2] = v.z; x[4*i+3] = v.w;
    }
    float fy = -1.f + (2.f*iy + 1.f) / 96.f;
    float fx = -1.f + (2.f*ix + 1.f) / 96.f;
    x[64] = (cy - fy) * 96.f;
    x[65] = (cx - fx) * 96.f;
    x[66] = cell[2*q]   * 96.f;
    x[67] = cell[2*q+1] * 96.f;

    // classifier (fp32 — flag precision is load-bearing)
    float l0 = sbc2[0], l1 = sbc2[1];
    for (int og = 0; og < 16; og++) {
        float4 a = make_float4(0.f,0.f,0.f,0.f);
        const float4* wp = (const float4*)(sWc + og*4);
        #pragma unroll
        for (int i = 0; i < INDIM; i++) {
            float4 wv = wp[i*16];
            a.x += x[i]*wv.x; a.y += x[i]*wv.y; a.z += x[i]*wv.z; a.w += x[i]*wv.w;
        }
        int o = og*4;
        float h0 = fmaxf(a.x + sbc1[o+0], 0.f);
        float h1 = fmaxf(a.y + sbc1[o+1], 0.f);
        float h2 = fmaxf(a.z + sbc1[o+2], 0.f);
        float h3 = fmaxf(a.w + sbc1[o+3], 0.f);
        l0 += h0*swc2[(o+0)*2] + h1*swc2[(o+1)*2] + h2*swc2[(o+2)*2] + h3*swc2[(o+3)*2];
        l1 += h0*swc2[(o+0)*2+1] + h1*swc2[(o+1)*2+1] + h2*swc2[(o+2)*2+1] + h3*swc2[(o+3)*2+1];
    }
    int flag = (l1 > l0) ? 1 : 0;

    // light MLP — only where used (flag==0)
    float p0 = 0.f, p1 = 0.f, p2 = 0.f;
    if (!flag) {
        p0 = sbl2[0]; p1 = sbl2[1]; p2 = sbl2[2];
        for (int og = 0; og < 16; og++) {
            float4 a = make_float4(0.f,0.f,0.f,0.f);
            const float4* wp = (const float4*)(sWl + og*4);
            #pragma unroll
            for (int i = 0; i < INDIM; i++) {
                float4 wv = wp[i*16];
                a.x += x[i]*wv.x; a.y += x[i]*wv.y; a.z += x[i]*wv.z; a.w += x[i]*wv.w;
            }
            int o = og*4;
            float h0 = fmaxf(a.x + sbl1[o+0], 0.f);
            float h1 = fmaxf(a.y + sbl1[o+1], 0.f);
            float h2 = fmaxf(a.z + sbl1[o+2], 0.f);
            float h3 = fmaxf(a.w + sbl1[o+3], 0.f);
            p0 += h0*swl2[(o+0)*3] + h1*swl2[(o+1)*3] + h2*swl2[(o+2)*3] + h3*swl2[(o+3)*3];
            p1 += h0*swl2[(o+0)*3+1] + h1*swl2[(o+1)*3+1] + h2*swl2[(o+2)*3+1] + h3*swl2[(o+3)*3+1];
            p2 += h0*swl2[(o+0)*3+2] + h1*swl2[(o+1)*3+2] + h2*swl2[(o+2)*3+2] + h3*swl2[(o+3)*3+2];
        }
    }

    // grid sample (bilinear, border, align_corners=False) on lr
    float gy = fminf(fmaxf((cy + 1.f) * 96.f * 0.5f - 0.5f, 0.f), 95.f);
    float gx = fminf(fmaxf((cx + 1.f) * 96.f * 0.5f - 0.5f, 0.f), 95.f);
    float y0f = floorf(gy), x0f = floorf(gx);
    float wy = gy - y0f, wx = gx - x0f;
    int y0 = (int)y0f, x0 = (int)x0f;
    int y1 = min(y0 + 1, HLR-1), x1 = min(x0 + 1, HLR-1);
    float w00 = (1.f-wy)*(1.f-wx), w01 = (1.f-wy)*wx, w10 = wy*(1.f-wx), w11 = wy*wx;
    float gs[3];
    #pragma unroll
    for (int c = 0; c < 3; c++) {
        const float* pl = lr + c*NPIX;
        gs[c] = pl[y0*HLR+x0]*w00 + pl[y0*HLR+x1]*w01
              + pl[y1*HLR+x0]*w10 + pl[y1*HLR+x1]*w11;
    }

    g_pred[3*q+0] = p0 + gs[0];
    g_pred[3*q+1] = p1 + gs[1];
    g_pred[3*q+2] = p2 + gs[2];
    g_flag[q] = flag;

    unsigned mask = __ballot_sync(0xffffffffu, flag);
    if (mask) {
        int lane = tid & 31;
        int leader = __ffs(mask) - 1;
        int basePos = 0;
        if (lane == leader) basePos = atomicAdd(&g_cnt, __popc(mask));
        basePos = __shfl_sync(0xffffffffu, basePos, leader);
        if (flag) g_hard[basePos + __popc(mask & ((1u << lane) - 1u))] = q;
    }
}

// ---------------- heavy MLP: tf32 mma.sync, cp.async double-buffered weights ----------------
// SMEM floats: As[128*260] | Bs[2][32*260] | sQ[128 ints]
#define SP    260
#define ASF   0
#define BSF   33280
#define BUFS  8320                 // 32*260 floats per buffer
#define SQF   (33280 + 2*8320)     // 49920
#define SMEM_HEAVY ((SQF + 128)*4 + 256)

__device__ __forceinline__ void cpasync16(unsigned s, const void* g) {
    asm volatile("cp.async.cg.shared.global [%0], [%1], 16;" :: "r"(s), "l"(g));
}
__device__ __forceinline__ void cp_commit() { asm volatile("cp.async.commit_group;"); }
template<int N> __device__ __forceinline__ void cp_wait() {
    asm volatile("cp.async.wait_group %0;" :: "n"(N));
}

__device__ __forceinline__ void mma8(float* d, unsigned a0, unsigned a1,
                                     unsigned a2, unsigned a3,
                                     unsigned b0, unsigned b1) {
    asm volatile(
        "mma.sync.aligned.m16n8k8.row.col.f32.tf32.tf32.f32 "
        "{%0,%1,%2,%3}, {%4,%5,%6,%7}, {%8,%9}, {%0,%1,%2,%3};"
        : "+f"(d[0]), "+f"(d[1]), "+f"(d[2]), "+f"(d[3])
        : "r"(a0), "r"(a1), "r"(a2), "r"(a3), "r"(b0), "r"(b1));
}

// stage one 32-row weight chunk into Bs buffer via cp.async (256 thr, 8 ops each)
__device__ __forceinline__ void stageW(unsigned bufAddr, const float* __restrict__ Wg, int kb) {
    int tid = threadIdx.x;
    #pragma unroll
    for (int j = 0; j < 8; j++) {
        int i = tid + j * 256;                     // 0..2047 float4 slots
        int row = i >> 6, c4 = i & 63;
        cpasync16(bufAddr + (unsigned)(row * SP + c4 * 4) * 4u,
                  Wg + (kb + row) * 256 + c4 * 4);
    }
    cp_commit();
}

// One layer IN-PLACE on As[128][SP]. Kw is padded multiple of 32 (96 or 256).
__device__ __forceinline__ void mma_layer(float* As,
                                          const float* __restrict__ Wg,
                                          const float* __restrict__ Bg,
                                          int Kw, float* Bs, unsigned bsAddr,
                                          int do_cvt) {
    int tid  = threadIdx.x;
    int w    = tid >> 5, lane = tid & 31;
    int g    = lane >> 2, r = lane & 3;
    int mbase = (w & 1) * 64;
    int nbase = (w >> 1) * 64;

    float acc[4][8][4];
    #pragma unroll
    for (int mt = 0; mt < 4; mt++)
        #pragma unroll
        for (int nt = 0; nt < 8; nt++)
            #pragma unroll
            for (int j = 0; j < 4; j++) acc[mt][nt][j] = 0.f;

    int nch = Kw >> 5;
    stageW(bsAddr, Wg, 0);                               // chunk 0 -> buf 0

    for (int c = 0; c < nch; c++) {
        int cur = c & 1;
        if (c + 1 < nch) {
            stageW(bsAddr + (unsigned)((1 - cur) * BUFS) * 4u, Wg, (c + 1) * 32);
            cp_wait<1>();
        } else {
            cp_wait<0>();
        }
        __syncthreads();                                 // staged data + prev-MMA ordering

        const float* Bc = Bs + cur * BUFS;
        int kb = c * 32;
        #pragma unroll
        for (int ks = 0; ks < 4; ks++) {
            const float* Ap = As + kb + ks * 8 + r;
            unsigned a[4][4];
            #pragma unroll
            for (int mt = 0; mt < 4; mt++) {
                int rowa = (mbase + mt * 16 + g) * SP;
                a[mt][0] = __float_as_uint(Ap[rowa]);
                a[mt][1] = __float_as_uint(Ap[rowa + 8 * SP]);
                a[mt][2] = __float_as_uint(Ap[rowa + 4]);
                a[mt][3] = __float_as_uint(Ap[rowa + 8 * SP + 4]);
            }
            const float* Br0 = Bc + (ks * 8 + r) * SP + nbase + g;
            const float* Br1 = Br0 + 4 * SP;
            #pragma unroll
            for (int nt = 0; nt < 8; nt++) {
                unsigned b0 = __float_as_uint(Br0[nt * 8]);
                unsigned b1 = __float_as_uint(Br1[nt * 8]);
                #pragma unroll
                for (int mt = 0; mt < 4; mt++)
                    mma8(acc[mt][nt], a[mt][0], a[mt][1], a[mt][2], a[mt][3], b0, b1);
            }
        }
        __syncthreads();                                 // MMA reads done before buf reuse
    }

    // epilogue: bias + relu (+ tf32 round), in-place write (post-sync above)
    #pragma unroll
    for (int nt = 0; nt < 8; nt++) {
        int c0 = nbase + nt * 8 + r * 2;
        float bb0 = __ldg(Bg + c0), bb1 = __ldg(Bg + c0 + 1);
        #pragma unroll
        for (int mt = 0; mt < 4; mt++) {
            int row0 = mbase + mt * 16 + g;
            float d0 = fmaxf(acc[mt][nt][0] + bb0, 0.f);
            float d1 = fmaxf(acc[mt][nt][1] + bb1, 0.f);
            float d2 = fmaxf(acc[mt][nt][2] + bb0, 0.f);
            float d3 = fmaxf(acc[mt][nt][3] + bb1, 0.f);
            if (do_cvt) { d0 = tf32r(d0); d1 = tf32r(d1); d2 = tf32r(d2); d3 = tf32r(d3); }
            *(float2*)(As + row0 * SP + c0)       = make_float2(d0, d1);
            *(float2*)(As + (row0 + 8) * SP + c0) = make_float2(d2, d3);
        }
    }
    __syncthreads();                                     // epilogue visible to next layer
}

__global__ __launch_bounds__(256, 1) void k_heavy(const float* __restrict__ coord,
                                                  const float* __restrict__ cell,
                                                  const float* __restrict__ bh1,
                                                  const float* __restrict__ bh2,
                                                  const float* __restrict__ bh3,
                                                  const float* __restrict__ wh4,
                                                  const float* __restrict__ bh4) {
    extern __shared__ float sm[];
    float* As = sm + ASF;
    float* Bs = sm + BSF;
    int*   sQ = (int*)(sm + SQF);
    unsigned bsAddr = (unsigned)__cvta_generic_to_shared(Bs);
    int tid = threadIdx.x;

    int n = *((volatile int*)&g_cnt);
    if (n <= 0) return;
    int tiles = (n + 127) >> 7;

    for (int t = blockIdx.x; t < tiles; t += gridDim.x) {
        __syncthreads();
        int base = t * 128;
        if (tid < 128) sQ[tid] = (base + tid < n) ? g_hard[base + tid] : -1;
        __syncthreads();

        // stage X (128 queries x 96 cols, tf32-rounded, cols 68..95 zero) into As
        {
            int m = tid >> 1, qpart = tid & 1;
            int qv = sQ[m];
            int q = qv < 0 ? 0 : qv;
            float cy = coord[2*q], cx = coord[2*q+1];
            int iy = (int)floorf((cy + 1.f)*0.5f*96.f); iy = min(max(iy,0), HLR-1);
            int ix = (int)floorf((cx + 1.f)*0.5f*96.f); ix = min(max(ix,0), HLR-1);
            int fb = (iy*HLR + ix)*CCH;
            float* dst = As + m * SP;
            #pragma unroll
            for (int j = 0; j < 8; j++) {
                float4 v = *(const float4*)(g_ft + fb + qpart*32 + j*4);
                v.x = tf32r(v.x); v.y = tf32r(v.y); v.z = tf32r(v.z); v.w = tf32r(v.w);
                *(float4*)(dst + qpart*32 + j*4) = v;
            }
            if (qpart) {
                float fy = -1.f + (2.f*iy + 1.f)/96.f;
                float fx = -1.f + (2.f*ix + 1.f)/96.f;
                float4 e;
                e.x = tf32r((cy - fy)*96.f);
                e.y = tf32r((cx - fx)*96.f);
                e.z = tf32r(cell[2*q]   * 96.f);
                e.w = tf32r(cell[2*q+1] * 96.f);
                *(float4*)(dst + 64) = e;
                #pragma unroll
                for (int j = 68; j < 96; j += 4)
                    *(float4*)(dst + j) = make_float4(0.f, 0.f, 0.f, 0.f);
            }
        }
        __syncthreads();

        mma_layer(As, g_w1r, bh1, 96,  Bs, bsAddr, 1);   // h1: 68(->96)->256
        mma_layer(As, g_w2r, bh2, 256, Bs, bsAddr, 1);   // h2: 256->256
        mma_layer(As, g_w3r, bh3, 256, Bs, bsAddr, 0);   // h3: 256->256 (fp32 out)

        // layer4: 256 -> 3 (fp32 SIMT) + writeback
        for (int i = tid; i < 384; i += 256) {
            int m = i & 127, c = i >> 7;
            const float* Ar = As + m * SP;
            float s0 = 0.f, s1 = 0.f, s2 = 0.f, s3 = 0.f;
            #pragma unroll 4
            for (int k = 0; k < 256; k += 4) {
                s0 += Ar[k+0] * wh4[(k+0)*3 + c];
                s1 += Ar[k+1] * wh4[(k+1)*3 + c];
                s2 += Ar[k+2] * wh4[(k+2)*3 + c];
                s3 += Ar[k+3] * wh4[(k+3)*3 + c];
            }
            int qv = sQ[m];
            if (qv >= 0) g_pred[qv*3 + c] += s0 + s1 + s2 + s3 + bh4[c];
        }
    }
}

// ---------------- refinement + output ----------------
__global__ __launch_bounds__(256) void k_refine(float* __restrict__ out, int out_size) {
    int q = blockIdx.x * 256 + threadIdx.x;
    if (q >= QTOT) return;
    int y = q / HS, x = q % HS;
    int flag = g_flag[q];
    float v0 = g_pred[3*q], v1 = g_pred[3*q+1], v2 = g_pred[3*q+2];

    if (y > 0 && y < HS-1 && x > 0 && x < HS-1 && flag == 0) {
        int fs = 0;
        #pragma unroll
        for (int dy = -1; dy <= 1; dy++)
            #pragma unroll
            for (int dx = -1; dx <= 1; dx++)
                fs += g_flag[(y+dy)*HS + x + dx];
        if (fs > 0) {
            float s0 = 0.f, s1 = 0.f, s2 = 0.f;
            #pragma unroll
            for (int dy = -1; dy <= 1; dy++)
                #pragma unroll
                for (int dx = -1; dx <= 1; dx++) {
                    int qq = (y+dy)*HS + x + dx;
                    s0 += g_pred[3*qq]; s1 += g_pred[3*qq+1]; s2 += g_pred[3*qq+2];
                }
            v0 = s0 / 9.f; v1 = s1 / 9.f; v2 = s2 / 9.f;
        }
    }
    out[3*q]   = v0;
    out[3*q+1] = v1;
    out[3*q+2] = v2;
    if (out_size >= 4*QTOT) out[3*QTOT + q] = (float)flag;
}

// ---------------- launcher ----------------
extern "C" void kernel_launch(void* const* d_in, const int* in_sizes, int n_in,
                              void* d_out, int out_size) {
    const float* lr    = (const float*)d_in[0];
    const float* coord = (const float*)d_in[1];
    const float* cell  = (const float*)d_in[2];
    const float* ew1 = (const float*)d_in[3];  const float* eb1 = (const float*)d_in[4];
    const float* ew2 = (const float*)d_in[5];  const float* eb2 = (const float*)d_in[6];
    const float* ew3 = (const float*)d_in[7];  const float* eb3 = (const float*)d_in[8];
    const float* wh1 = (const float*)d_in[9];  const float* bh1 = (const float*)d_in[10];
    const float* wh2 = (const float*)d_in[11]; const float* bh2 = (const float*)d_in[12];
    const float* wh3 = (const float*)d_in[13]; const float* bh3 = (const float*)d_in[14];
    const float* wh4 = (const float*)d_in[15]; const float* bh4 = (const float*)d_in[16];
    const float* wl1 = (const float*)d_in[17]; const float* bl1 = (const float*)d_in[18];
    const float* wl2 = (const float*)d_in[19]; const float* bl2 = (const float*)d_in[20];
    const float* wc1 = (const float*)d_in[21]; const float* bc1 = (const float*)d_in[22];
    const float* wc2 = (const float*)d_in[23]; const float* bc2 = (const float*)d_in[24];

    (void)cudaFuncSetAttribute(k_heavy, cudaFuncAttributeMaxDynamicSharedMemorySize, SMEM_HEAVY);

    k_prep<<<(96*256 + 131072 + 255)/256, 256>>>(wh1, wh2, wh3);
    k_conv1<<<(CCH*NPIX + 255)/256, 256>>>(lr, ew1, eb1);
    k_conv64<<<dim3(36, 4), 256>>>(ew2, eb2, 0);
    k_conv64<<<dim3(36, 4), 256>>>(ew3, eb3, 1);
    k_query<<<QTOT/128, 128>>>(coord, cell, lr,
                               wl1, bl1, wl2, bl2, wc1, bc1, wc2, bc2);
    k_heavy<<<148, 256, SMEM_HEAVY>>>(coord, cell, bh1, bh2, bh3, wh4, bh4);
    k_refine<<<QTOT/256, 256>>>((float*)d_out, out_size);
}